// round 7
// baseline (speedup 1.0000x reference)
#include <cuda_runtime.h>
#include <cuda_pipeline.h>

// GACRF fused: softmax(C=19) -> encode(G=8) -> 3x3 dynamic filter -> decode ->
// logit - result.  Single kernel, 64x16 tile + 1px halo in smem.
//
// R6: F-tap prefetch. Phase-2's 9 F loads don't depend on phase 1, so they are
// issued as cp.async into a shared F tile at kernel entry (zero register cost)
// and complete behind phase 1's softmax/encode stream. Each thread reads back
// only its own chunks -> __pipeline_wait_prior(0), no extra barrier. Qg + F
// tile = 78.3KB -> dynamic smem (2 CTAs/SM still).
//
// Shapes (fixed): b=4, C=19, G=8, H=W=512, K=3.

#define BATCH 4
#define NC 19
#define NG 8
#define IMH 512
#define IMW 512
#define HW (IMH * IMW)

#define TW 64            // output tile width
#define TH 16            // output tile height
#define EH (TH + 2)      // 18 extended rows (global y0-1 .. y0+16)
#define EWP 72           // padded extended width, covers global [x0-4, x0+68)
#define NPAIR (EH * 9)   // 162 phase-1 threads, each: 2 adjacent 4-px groups
#define NTHREADS 256

#define QG_BYTES  (NG * EH * EWP * 4)        // 41472
#define FSH_BYTES (9 * TH * TW * 4)          // 36864
#define SMEM_DYN  (QG_BYTES + FSH_BYTES)     // 78336

__global__ __launch_bounds__(NTHREADS, 2) void gacrf_fused_kernel(
    const float* __restrict__ Fk,     // [b,9,H,W]
    const float* __restrict__ logit,  // [b,C,H,W]
    const float* __restrict__ matrix, // [G,C]
    float* __restrict__ out)          // [b,C,H,W]
{
    extern __shared__ __align__(16) char smem_dyn[];
    float (*Qg)[EH][EWP] = reinterpret_cast<float (*)[EH][EWP]>(smem_dyn);
    float (*Fsh)[TH][TW] = reinterpret_cast<float (*)[TH][TW]>(smem_dyn + QG_BYTES);
    __shared__ float Esh[NG][NC];

    const int tid = threadIdx.x;
    const int bx = blockIdx.x, by = blockIdx.y, bz = blockIdx.z;
    const int x0 = bx * TW;
    const int y0 = by * TH;

    // ---- Prefetch F taps for this CTA's output tile (cp.async, no regs) ----
    const int p2y  = tid >> 4;           // 0..15 (phase-2 row)
    const int p2xg = (tid & 15) << 2;    // 0,4,..,60 (phase-2 col group)
    {
        const float* __restrict__ fp =
            Fk + (size_t)bz * 9 * HW + (size_t)(y0 + p2y) * IMW + (x0 + p2xg);
        #pragma unroll
        for (int k = 0; k < 9; k++)
            __pipeline_memcpy_async(&Fsh[k][p2y][p2xg], fp + (size_t)k * HW, 16);
        __pipeline_commit();
    }

    // ---- E = softmax over G of 100*matrix ----
    if (tid < NC) {
        const int c = tid;
        float m[NG];
        float mx = -1e30f;
        #pragma unroll
        for (int g = 0; g < NG; g++) {
            m[g] = 100.0f * matrix[g * NC + c];
            mx = fmaxf(mx, m[g]);
        }
        float s = 0.0f;
        #pragma unroll
        for (int g = 0; g < NG; g++) { m[g] = __expf(m[g] - mx); s += m[g]; }
        const float r = 1.0f / s;
        #pragma unroll
        for (int g = 0; g < NG; g++) Esh[g][c] = m[g] * r;
    }
    __syncthreads();

    const float* __restrict__ logit_b = logit + (size_t)bz * NC * HW;

    // ---- Phase 1: softmax+encode, ONE pass, 8 px (2 groups) per thread ----
    if (tid < NPAIR) {
        const int r   = tid / 9;
        const int j   = tid - r * 9;
        const int gy  = y0 + r - 1;
        const int gxb = x0 - 4 + 8 * j;

        const bool rowok = (unsigned)gy < IMH;
        const bool vA = rowok && ((unsigned)gxb       < IMW);
        const bool vB = rowok && ((unsigned)(gxb + 4) < IMW);

        float4 aA[NG], aB[NG];
        #pragma unroll
        for (int g = 0; g < NG; g++) {
            aA[g] = make_float4(0.f, 0.f, 0.f, 0.f);
            aB[g] = make_float4(0.f, 0.f, 0.f, 0.f);
        }
        float4 sA = make_float4(0.f, 0.f, 0.f, 0.f);
        float4 sB = make_float4(0.f, 0.f, 0.f, 0.f);

        const float* __restrict__ p = logit_b + (size_t)gy * IMW + gxb;
        const float4 z4 = make_float4(0.f, 0.f, 0.f, 0.f);

        #pragma unroll
        for (int c = 0; c < NC; c++) {
            const float4 vA4 = vA ? __ldg((const float4*)(p + (size_t)c * HW))     : z4;
            const float4 vB4 = vB ? __ldg((const float4*)(p + (size_t)c * HW + 4)) : z4;
            const float ea0 = __expf(vA4.x), ea1 = __expf(vA4.y);
            const float ea2 = __expf(vA4.z), ea3 = __expf(vA4.w);
            const float eb0 = __expf(vB4.x), eb1 = __expf(vB4.y);
            const float eb2 = __expf(vB4.z), eb3 = __expf(vB4.w);
            sA.x += ea0; sA.y += ea1; sA.z += ea2; sA.w += ea3;
            sB.x += eb0; sB.y += eb1; sB.z += eb2; sB.w += eb3;
            #pragma unroll
            for (int g = 0; g < NG; g++) {
                const float E = Esh[g][c];
                aA[g].x = fmaf(E, ea0, aA[g].x);
                aA[g].y = fmaf(E, ea1, aA[g].y);
                aA[g].z = fmaf(E, ea2, aA[g].z);
                aA[g].w = fmaf(E, ea3, aA[g].w);
                aB[g].x = fmaf(E, eb0, aB[g].x);
                aB[g].y = fmaf(E, eb1, aB[g].y);
                aB[g].z = fmaf(E, eb2, aB[g].z);
                aB[g].w = fmaf(E, eb3, aB[g].w);
            }
        }
        const float ra0 = __frcp_rn(sA.x), ra1 = __frcp_rn(sA.y);
        const float ra2 = __frcp_rn(sA.z), ra3 = __frcp_rn(sA.w);
        const float rb0 = __frcp_rn(sB.x), rb1 = __frcp_rn(sB.y);
        const float rb2 = __frcp_rn(sB.z), rb3 = __frcp_rn(sB.w);

        #pragma unroll
        for (int g = 0; g < NG; g++) {
            float4 oA = z4, oB = z4;
            if (vA) { oA.x = aA[g].x * ra0; oA.y = aA[g].y * ra1;
                      oA.z = aA[g].z * ra2; oA.w = aA[g].w * ra3; }
            if (vB) { oB.x = aB[g].x * rb0; oB.y = aB[g].y * rb1;
                      oB.z = aB[g].z * rb2; oB.w = aB[g].w * rb3; }
            *(float4*)&Qg[g][r][8 * j]     = oA;
            *(float4*)&Qg[g][r][8 * j + 4] = oB;
        }
    }
    __syncthreads();

    // ---- Phase 2: 3x3 filter + decode + subtract, 4 px/thread ----
    {
        const int y  = p2y;
        const int xg = p2xg;
        const int gy = y0 + y;

        // F taps: prefetched by THIS thread -> wait only on own copies
        __pipeline_wait_prior(0);
        float4 f4[9];
        #pragma unroll
        for (int k = 0; k < 9; k++) f4[k] = *(const float4*)&Fsh[k][y][xg];

        float4 filt[NG];
        #pragma unroll
        for (int g = 0; g < NG; g++) filt[g] = make_float4(0.f, 0.f, 0.f, 0.f);

        #pragma unroll
        for (int g = 0; g < NG; g++) {
            #pragma unroll
            for (int dr = 0; dr < 3; dr++) {
                const float* __restrict__ qrow = &Qg[g][y + dr][xg + 3];
                const float  q0 = qrow[0];
                const float4 qm = *(const float4*)(qrow + 1);
                const float  q5 = qrow[5];
                const float4 fa = f4[dr * 3 + 0];
                const float4 fb = f4[dr * 3 + 1];
                const float4 fc = f4[dr * 3 + 2];
                filt[g].x = fmaf(fa.x, q0,   fmaf(fb.x, qm.x, fmaf(fc.x, qm.y, filt[g].x)));
                filt[g].y = fmaf(fa.y, qm.x, fmaf(fb.y, qm.y, fmaf(fc.y, qm.z, filt[g].y)));
                filt[g].z = fmaf(fa.z, qm.y, fmaf(fb.z, qm.z, fmaf(fc.z, qm.w, filt[g].z)));
                filt[g].w = fmaf(fa.w, qm.z, fmaf(fb.w, qm.w, fmaf(fc.w, q5,   filt[g].w)));
            }
        }

        const float* __restrict__ lp = logit_b + (size_t)gy * IMW + (x0 + xg);
        float* __restrict__       op = out + (size_t)bz * NC * HW
                                           + (size_t)gy * IMW + (x0 + xg);
        #pragma unroll
        for (int c = 0; c < NC; c++) {
            float4 a = make_float4(0.f, 0.f, 0.f, 0.f);
            #pragma unroll
            for (int g = 0; g < NG; g++) {
                const float E = Esh[g][c];
                a.x = fmaf(E, filt[g].x, a.x);
                a.y = fmaf(E, filt[g].y, a.y);
                a.z = fmaf(E, filt[g].z, a.z);
                a.w = fmaf(E, filt[g].w, a.w);
            }
            const float4 l4 = __ldg((const float4*)(lp + (size_t)c * HW));
            float4 o;
            o.x = l4.x - a.x; o.y = l4.y - a.y;
            o.z = l4.z - a.z; o.w = l4.w - a.w;
            __stcs((float4*)(op + (size_t)c * HW), o);
        }
    }
}

extern "C" void kernel_launch(void* const* d_in, const int* in_sizes, int n_in,
                              void* d_out, int out_size) {
    // Bind inputs by element count (robust to ordering):
    //   F: 9437184, logit: 19922944, matrix: 152
    const float* F      = nullptr;
    const float* logit  = nullptr;
    const float* matrix = nullptr;
    for (int i = 0; i < n_in; i++) {
        if (in_sizes[i] == 9437184)       F      = (const float*)d_in[i];
        else if (in_sizes[i] == 19922944) logit  = (const float*)d_in[i];
        else if (in_sizes[i] == 152)      matrix = (const float*)d_in[i];
    }
    float* out = (float*)d_out;

    cudaFuncSetAttribute(gacrf_fused_kernel,
                         cudaFuncAttributeMaxDynamicSharedMemorySize, SMEM_DYN);

    dim3 grid(IMW / TW, IMH / TH, BATCH);   // (8, 32, 4)
    gacrf_fused_kernel<<<grid, NTHREADS, SMEM_DYN>>>(F, logit, matrix, out);
}

// round 8
// speedup vs baseline: 1.0242x; 1.0242x over previous
#include <cuda_runtime.h>

// GACRF fused: softmax(C=19) -> encode(G=8) -> 3x3 dynamic filter -> decode ->
// logit - result.  Single kernel, 64x16 tile + 1px halo in smem.
//
// R7: packed fp32 math. Encode/decode einsums (the dominant instruction block:
// 152 FMA/pixel encode + 152 decode) now use Blackwell fma.rn.f32x2 (FFMA2,
// 2 lanes/inst, bit-identical per lane). E is stored duplicated as (E,E)
// float2 in smem so each FFMA2 multiplier is a single broadcast LDS.64.
// R6's cp.async F-prefetch reverted (measured slightly negative).
//
// Shapes (fixed): b=4, C=19, G=8, H=W=512, K=3.

#define BATCH 4
#define NC 19
#define NG 8
#define IMH 512
#define IMW 512
#define HW (IMH * IMW)

#define TW 64            // output tile width
#define TH 16            // output tile height
#define EH (TH + 2)      // 18 extended rows (global y0-1 .. y0+16)
#define EWP 72           // padded extended width, covers global [x0-4, x0+68)
#define NPAIR (EH * 9)   // 162 phase-1 threads, each: 2 adjacent 4-px groups
#define NTHREADS 256

// ---- packed f32x2 helpers (per-lane IEEE identical to scalar) ----
__device__ __forceinline__ float2 ffma2(float2 a, float2 b, float2 c) {
    float2 d;
    asm("fma.rn.f32x2 %0, %1, %2, %3;"
        : "=l"(*reinterpret_cast<unsigned long long*>(&d))
        : "l"(*reinterpret_cast<unsigned long long*>(&a)),
          "l"(*reinterpret_cast<unsigned long long*>(&b)),
          "l"(*reinterpret_cast<unsigned long long*>(&c)));
    return d;
}
__device__ __forceinline__ float2 fadd2(float2 a, float2 b) {
    float2 d;
    asm("add.rn.f32x2 %0, %1, %2;"
        : "=l"(*reinterpret_cast<unsigned long long*>(&d))
        : "l"(*reinterpret_cast<unsigned long long*>(&a)),
          "l"(*reinterpret_cast<unsigned long long*>(&b)));
    return d;
}
__device__ __forceinline__ float2 fmul2(float2 a, float2 b) {
    float2 d;
    asm("mul.rn.f32x2 %0, %1, %2;"
        : "=l"(*reinterpret_cast<unsigned long long*>(&d))
        : "l"(*reinterpret_cast<unsigned long long*>(&a)),
          "l"(*reinterpret_cast<unsigned long long*>(&b)));
    return d;
}

__global__ __launch_bounds__(NTHREADS, 2) void gacrf_fused_kernel(
    const float* __restrict__ Fk,     // [b,9,H,W]
    const float* __restrict__ logit,  // [b,C,H,W]
    const float* __restrict__ matrix, // [G,C]
    float* __restrict__ out)          // [b,C,H,W]
{
    __shared__ float2 EshD[NC][NG];                   // (E,E) duplicated, 1216 B
    __shared__ __align__(16) float Qg[NG][EH][EWP];   // 41472 B

    const int tid = threadIdx.x;
    const int bx = blockIdx.x, by = blockIdx.y, bz = blockIdx.z;

    // ---- E = softmax over G of 100*matrix (stored duplicated for FFMA2) ----
    if (tid < NC) {
        const int c = tid;
        float m[NG];
        float mx = -1e30f;
        #pragma unroll
        for (int g = 0; g < NG; g++) {
            m[g] = 100.0f * matrix[g * NC + c];
            mx = fmaxf(mx, m[g]);
        }
        float s = 0.0f;
        #pragma unroll
        for (int g = 0; g < NG; g++) { m[g] = __expf(m[g] - mx); s += m[g]; }
        const float r = 1.0f / s;
        #pragma unroll
        for (int g = 0; g < NG; g++) {
            const float v = m[g] * r;
            EshD[c][g] = make_float2(v, v);
        }
    }
    __syncthreads();

    const int x0 = bx * TW;
    const int y0 = by * TH;
    const float* __restrict__ logit_b = logit + (size_t)bz * NC * HW;

    // ---- Phase 1: softmax+encode, ONE pass, 8 px (2 groups) per thread ----
    if (tid < NPAIR) {
        const int r   = tid / 9;
        const int j   = tid - r * 9;
        const int gy  = y0 + r - 1;
        const int gxb = x0 - 4 + 8 * j;

        const bool rowok = (unsigned)gy < IMH;
        const bool vA = rowok && ((unsigned)gxb       < IMW);
        const bool vB = rowok && ((unsigned)(gxb + 4) < IMW);

        const float2 z2 = make_float2(0.f, 0.f);
        float2 aA01[NG], aA23[NG], aB01[NG], aB23[NG];
        #pragma unroll
        for (int g = 0; g < NG; g++) {
            aA01[g] = z2; aA23[g] = z2; aB01[g] = z2; aB23[g] = z2;
        }
        float2 sA01 = z2, sA23 = z2, sB01 = z2, sB23 = z2;

        const float* __restrict__ p = logit_b + (size_t)gy * IMW + gxb;
        const float4 z4 = make_float4(0.f, 0.f, 0.f, 0.f);

        #pragma unroll
        for (int c = 0; c < NC; c++) {
            const float4 vA4 = vA ? __ldg((const float4*)(p + (size_t)c * HW))     : z4;
            const float4 vB4 = vB ? __ldg((const float4*)(p + (size_t)c * HW + 4)) : z4;
            const float2 eA01 = make_float2(__expf(vA4.x), __expf(vA4.y));
            const float2 eA23 = make_float2(__expf(vA4.z), __expf(vA4.w));
            const float2 eB01 = make_float2(__expf(vB4.x), __expf(vB4.y));
            const float2 eB23 = make_float2(__expf(vB4.z), __expf(vB4.w));
            sA01 = fadd2(sA01, eA01); sA23 = fadd2(sA23, eA23);
            sB01 = fadd2(sB01, eB01); sB23 = fadd2(sB23, eB23);
            #pragma unroll
            for (int g = 0; g < NG; g++) {
                const float2 E2 = EshD[c][g];
                aA01[g] = ffma2(E2, eA01, aA01[g]);
                aA23[g] = ffma2(E2, eA23, aA23[g]);
                aB01[g] = ffma2(E2, eB01, aB01[g]);
                aB23[g] = ffma2(E2, eB23, aB23[g]);
            }
        }
        const float2 rA01 = make_float2(__frcp_rn(sA01.x), __frcp_rn(sA01.y));
        const float2 rA23 = make_float2(__frcp_rn(sA23.x), __frcp_rn(sA23.y));
        const float2 rB01 = make_float2(__frcp_rn(sB01.x), __frcp_rn(sB01.y));
        const float2 rB23 = make_float2(__frcp_rn(sB23.x), __frcp_rn(sB23.y));

        #pragma unroll
        for (int g = 0; g < NG; g++) {
            float4 oA = z4, oB = z4;
            if (vA) {
                const float2 a01 = fmul2(aA01[g], rA01);
                const float2 a23 = fmul2(aA23[g], rA23);
                oA = make_float4(a01.x, a01.y, a23.x, a23.y);
            }
            if (vB) {
                const float2 b01 = fmul2(aB01[g], rB01);
                const float2 b23 = fmul2(aB23[g], rB23);
                oB = make_float4(b01.x, b01.y, b23.x, b23.y);
            }
            *(float4*)&Qg[g][r][8 * j]     = oA;
            *(float4*)&Qg[g][r][8 * j + 4] = oB;
        }
    }
    __syncthreads();

    // ---- Phase 2: 3x3 filter + decode + subtract, 4 px/thread ----
    {
        const int y  = tid >> 4;           // 0..15
        const int xg = (tid & 15) << 2;    // 0,4,..,60
        const int gy = y0 + y;

        const float* __restrict__ F_b = Fk + (size_t)bz * 9 * HW;

        // 9 per-pixel filter taps (streaming: no reuse -> ldcs)
        float4 f4[9];
        const float* __restrict__ fp = F_b + (size_t)gy * IMW + (x0 + xg);
        #pragma unroll
        for (int k = 0; k < 9; k++) f4[k] = __ldcs((const float4*)(fp + (size_t)k * HW));

        const float2 z2 = make_float2(0.f, 0.f);
        float2 filt01[NG], filt23[NG];
        #pragma unroll
        for (int g = 0; g < NG; g++) { filt01[g] = z2; filt23[g] = z2; }

        #pragma unroll
        for (int g = 0; g < NG; g++) {
            #pragma unroll
            for (int dr = 0; dr < 3; dr++) {
                const float* __restrict__ qrow = &Qg[g][y + dr][xg + 3];
                const float  q0 = qrow[0];
                const float4 qm = *(const float4*)(qrow + 1);
                const float  q5 = qrow[5];
                const float4 fa = f4[dr * 3 + 0];
                const float4 fb = f4[dr * 3 + 1];
                const float4 fc = f4[dr * 3 + 2];
                filt01[g].x = fmaf(fa.x, q0,   fmaf(fb.x, qm.x, fmaf(fc.x, qm.y, filt01[g].x)));
                filt01[g].y = fmaf(fa.y, qm.x, fmaf(fb.y, qm.y, fmaf(fc.y, qm.z, filt01[g].y)));
                filt23[g].x = fmaf(fa.z, qm.y, fmaf(fb.z, qm.z, fmaf(fc.z, qm.w, filt23[g].x)));
                filt23[g].y = fmaf(fa.w, qm.z, fmaf(fb.w, qm.w, fmaf(fc.w, q5,   filt23[g].y)));
            }
        }

        const float* __restrict__ lp = logit_b + (size_t)gy * IMW + (x0 + xg);
        float* __restrict__       op = out + (size_t)bz * NC * HW
                                           + (size_t)gy * IMW + (x0 + xg);
        #pragma unroll
        for (int c = 0; c < NC; c++) {
            float2 a01 = z2, a23 = z2;
            #pragma unroll
            for (int g = 0; g < NG; g++) {
                const float2 E2 = EshD[c][g];
                a01 = ffma2(E2, filt01[g], a01);
                a23 = ffma2(E2, filt23[g], a23);
            }
            const float4 l4 = __ldg((const float4*)(lp + (size_t)c * HW));
            float4 o;
            o.x = l4.x - a01.x; o.y = l4.y - a01.y;
            o.z = l4.z - a23.x; o.w = l4.w - a23.y;
            __stcs((float4*)(op + (size_t)c * HW), o);
        }
    }
}

extern "C" void kernel_launch(void* const* d_in, const int* in_sizes, int n_in,
                              void* d_out, int out_size) {
    // Bind inputs by element count (robust to ordering):
    //   F: 9437184, logit: 19922944, matrix: 152
    const float* F      = nullptr;
    const float* logit  = nullptr;
    const float* matrix = nullptr;
    for (int i = 0; i < n_in; i++) {
        if (in_sizes[i] == 9437184)       F      = (const float*)d_in[i];
        else if (in_sizes[i] == 19922944) logit  = (const float*)d_in[i];
        else if (in_sizes[i] == 152)      matrix = (const float*)d_in[i];
    }
    float* out = (float*)d_out;

    dim3 grid(IMW / TW, IMH / TH, BATCH);   // (8, 32, 4)
    gacrf_fused_kernel<<<grid, NTHREADS>>>(F, logit, matrix, out);
}

// round 9
// speedup vs baseline: 1.0519x; 1.0270x over previous
#include <cuda_runtime.h>

// GACRF fused: softmax(C=19) -> encode(G=8) -> 3x3 dynamic filter -> decode ->
// logit - result.  Single kernel, 64x16 tile + 1px halo in smem.
//
// R8: occupancy 2 -> 3 CTAs/SM. Evidence: issue 32%, all pipes <35%, 68% of
// cycles zero eligible warps -> latency-bound on warp count. Register diet:
//   - phase 1 processes its two 4-px groups in TWO sequential fully-unrolled
//     passes (16 float2 accumulators live instead of 32),
//   - phase 2 stages F taps 3-at-a-time (per dr) instead of 9 up front.
// FFMA2 packed math kept from R7 (fewer issue slots = more room at 3 CTAs).
//
// Shapes (fixed): b=4, C=19, G=8, H=W=512, K=3.

#define BATCH 4
#define NC 19
#define NG 8
#define IMH 512
#define IMW 512
#define HW (IMH * IMW)

#define TW 64            // output tile width
#define TH 16            // output tile height
#define EH (TH + 2)      // 18 extended rows (global y0-1 .. y0+16)
#define EWP 72           // padded extended width, covers global [x0-4, x0+68)
#define NPAIR (EH * 9)   // 162 phase-1 threads, each owns 2 adjacent 4-px groups
#define NTHREADS 256

// ---- packed f32x2 helpers (per-lane IEEE identical to scalar) ----
__device__ __forceinline__ float2 ffma2(float2 a, float2 b, float2 c) {
    float2 d;
    asm("fma.rn.f32x2 %0, %1, %2, %3;"
        : "=l"(*reinterpret_cast<unsigned long long*>(&d))
        : "l"(*reinterpret_cast<unsigned long long*>(&a)),
          "l"(*reinterpret_cast<unsigned long long*>(&b)),
          "l"(*reinterpret_cast<unsigned long long*>(&c)));
    return d;
}
__device__ __forceinline__ float2 fadd2(float2 a, float2 b) {
    float2 d;
    asm("add.rn.f32x2 %0, %1, %2;"
        : "=l"(*reinterpret_cast<unsigned long long*>(&d))
        : "l"(*reinterpret_cast<unsigned long long*>(&a)),
          "l"(*reinterpret_cast<unsigned long long*>(&b)));
    return d;
}
__device__ __forceinline__ float2 fmul2(float2 a, float2 b) {
    float2 d;
    asm("mul.rn.f32x2 %0, %1, %2;"
        : "=l"(*reinterpret_cast<unsigned long long*>(&d))
        : "l"(*reinterpret_cast<unsigned long long*>(&a)),
          "l"(*reinterpret_cast<unsigned long long*>(&b)));
    return d;
}

__global__ __launch_bounds__(NTHREADS, 3) void gacrf_fused_kernel(
    const float* __restrict__ Fk,     // [b,9,H,W]
    const float* __restrict__ logit,  // [b,C,H,W]
    const float* __restrict__ matrix, // [G,C]
    float* __restrict__ out)          // [b,C,H,W]
{
    __shared__ float2 EshD[NC][NG];                   // (E,E) duplicated, 1216 B
    __shared__ __align__(16) float Qg[NG][EH][EWP];   // 41472 B

    const int tid = threadIdx.x;
    const int bx = blockIdx.x, by = blockIdx.y, bz = blockIdx.z;

    // ---- E = softmax over G of 100*matrix (stored duplicated for FFMA2) ----
    if (tid < NC) {
        const int c = tid;
        float m[NG];
        float mx = -1e30f;
        #pragma unroll
        for (int g = 0; g < NG; g++) {
            m[g] = 100.0f * matrix[g * NC + c];
            mx = fmaxf(mx, m[g]);
        }
        float s = 0.0f;
        #pragma unroll
        for (int g = 0; g < NG; g++) { m[g] = __expf(m[g] - mx); s += m[g]; }
        const float r = 1.0f / s;
        #pragma unroll
        for (int g = 0; g < NG; g++) {
            const float v = m[g] * r;
            EshD[c][g] = make_float2(v, v);
        }
    }
    __syncthreads();

    const int x0 = bx * TW;
    const int y0 = by * TH;
    const float* __restrict__ logit_b = logit + (size_t)bz * NC * HW;

    // ---- Phase 1: softmax+encode; 2 sequential 4-px passes per thread ----
    if (tid < NPAIR) {
        const int r  = tid / 9;
        const int j  = tid - r * 9;
        const int gy = y0 + r - 1;
        const bool rowok = (unsigned)gy < IMH;
        const float2 z2 = make_float2(0.f, 0.f);
        const float4 z4 = make_float4(0.f, 0.f, 0.f, 0.f);

        #pragma unroll
        for (int pass = 0; pass < 2; pass++) {
            const int gxb = x0 - 4 + 8 * j + 4 * pass;
            // 4-aligned group vs 512 image: fully inside or fully outside
            const bool v = rowok && ((unsigned)gxb < IMW);

            float2 a01[NG], a23[NG];
            #pragma unroll
            for (int g = 0; g < NG; g++) { a01[g] = z2; a23[g] = z2; }
            float2 s01 = z2, s23 = z2;

            const float* __restrict__ p = logit_b + (size_t)gy * IMW + gxb;

            #pragma unroll
            for (int c = 0; c < NC; c++) {
                const float4 v4 = v ? __ldg((const float4*)(p + (size_t)c * HW)) : z4;
                const float2 e01 = make_float2(__expf(v4.x), __expf(v4.y));
                const float2 e23 = make_float2(__expf(v4.z), __expf(v4.w));
                s01 = fadd2(s01, e01);
                s23 = fadd2(s23, e23);
                #pragma unroll
                for (int g = 0; g < NG; g++) {
                    const float2 E2 = EshD[c][g];
                    a01[g] = ffma2(E2, e01, a01[g]);
                    a23[g] = ffma2(E2, e23, a23[g]);
                }
            }
            const float2 r01 = make_float2(__frcp_rn(s01.x), __frcp_rn(s01.y));
            const float2 r23 = make_float2(__frcp_rn(s23.x), __frcp_rn(s23.y));

            #pragma unroll
            for (int g = 0; g < NG; g++) {
                float4 o = z4;
                if (v) {
                    const float2 q01 = fmul2(a01[g], r01);
                    const float2 q23 = fmul2(a23[g], r23);
                    o = make_float4(q01.x, q01.y, q23.x, q23.y);
                }
                *(float4*)&Qg[g][r][8 * j + 4 * pass] = o;
            }
        }
    }
    __syncthreads();

    // ---- Phase 2: 3x3 filter + decode + subtract, 4 px/thread ----
    {
        const int y  = tid >> 4;           // 0..15
        const int xg = (tid & 15) << 2;    // 0,4,..,60
        const int gy = y0 + y;

        const float* __restrict__ fp =
            Fk + (size_t)bz * 9 * HW + (size_t)gy * IMW + (x0 + xg);

        const float2 z2 = make_float2(0.f, 0.f);
        float2 filt01[NG], filt23[NG];
        #pragma unroll
        for (int g = 0; g < NG; g++) { filt01[g] = z2; filt23[g] = z2; }

        // dr-outer: stage 3 F taps at a time (register diet for 3 CTAs/SM)
        #pragma unroll
        for (int dr = 0; dr < 3; dr++) {
            const float4 fa = __ldcs((const float4*)(fp + (size_t)(dr * 3 + 0) * HW));
            const float4 fb = __ldcs((const float4*)(fp + (size_t)(dr * 3 + 1) * HW));
            const float4 fc = __ldcs((const float4*)(fp + (size_t)(dr * 3 + 2) * HW));
            #pragma unroll
            for (int g = 0; g < NG; g++) {
                const float* __restrict__ qrow = &Qg[g][y + dr][xg + 3];
                const float  q0 = qrow[0];
                const float4 qm = *(const float4*)(qrow + 1);
                const float  q5 = qrow[5];
                filt01[g].x = fmaf(fa.x, q0,   fmaf(fb.x, qm.x, fmaf(fc.x, qm.y, filt01[g].x)));
                filt01[g].y = fmaf(fa.y, qm.x, fmaf(fb.y, qm.y, fmaf(fc.y, qm.z, filt01[g].y)));
                filt23[g].x = fmaf(fa.z, qm.y, fmaf(fb.z, qm.z, fmaf(fc.z, qm.w, filt23[g].x)));
                filt23[g].y = fmaf(fa.w, qm.z, fmaf(fb.w, qm.w, fmaf(fc.w, q5,   filt23[g].y)));
            }
        }

        const float* __restrict__ lp = logit_b + (size_t)gy * IMW + (x0 + xg);
        float* __restrict__       op = out + (size_t)bz * NC * HW
                                           + (size_t)gy * IMW + (x0 + xg);
        #pragma unroll
        for (int c = 0; c < NC; c++) {
            float2 a01 = z2, a23 = z2;
            #pragma unroll
            for (int g = 0; g < NG; g++) {
                const float2 E2 = EshD[c][g];
                a01 = ffma2(E2, filt01[g], a01);
                a23 = ffma2(E2, filt23[g], a23);
            }
            const float4 l4 = __ldg((const float4*)(lp + (size_t)c * HW));
            float4 o;
            o.x = l4.x - a01.x; o.y = l4.y - a01.y;
            o.z = l4.z - a23.x; o.w = l4.w - a23.y;
            __stcs((float4*)(op + (size_t)c * HW), o);
        }
    }
}

extern "C" void kernel_launch(void* const* d_in, const int* in_sizes, int n_in,
                              void* d_out, int out_size) {
    // Bind inputs by element count (robust to ordering):
    //   F: 9437184, logit: 19922944, matrix: 152
    const float* F      = nullptr;
    const float* logit  = nullptr;
    const float* matrix = nullptr;
    for (int i = 0; i < n_in; i++) {
        if (in_sizes[i] == 9437184)       F      = (const float*)d_in[i];
        else if (in_sizes[i] == 19922944) logit  = (const float*)d_in[i];
        else if (in_sizes[i] == 152)      matrix = (const float*)d_in[i];
    }
    float* out = (float*)d_out;

    dim3 grid(IMW / TW, IMH / TH, BATCH);   // (8, 32, 4)
    gacrf_fused_kernel<<<grid, NTHREADS>>>(F, logit, matrix, out);
}